// round 2
// baseline (speedup 1.0000x reference)
#include <cuda_runtime.h>

#define EPS 1e-5f
#define NGRAPH 128
#define EMAX 800000
#define NMAX 50000

// ---------------- scratch (__device__ globals; no allocation allowed) -------
__device__ int g_is64_ei, g_is64_bt;
__device__ int g_hist[NGRAPH];
__device__ int g_off[NGRAPH + 1];
__device__ int g_cursor[NGRAPH];
__device__ int g_seg[EMAX];
__device__ int g_col[EMAX];
__device__ int g_row[EMAX];
__device__ int g_perm[EMAX];
__device__ int g_segS[EMAX];
__device__ int g_colS[EMAX];
__device__ int g_rowS[EMAX];
__device__ __align__(16) float g_P[NMAX * 256];   // emb @ W1[:64 ,:]
__device__ __align__(16) float g_Q[NMAX * 256];   // emb @ W1[64:,:]
__device__ __align__(16) float g_h2[(size_t)EMAX * 64];
__device__ __align__(16) float g_mean1[NGRAPH * 256];
__device__ __align__(16) float g_rstd1[NGRAPH * 256];
__device__ __align__(16) float g_mean2[NGRAPH * 64];
__device__ __align__(16) float g_rstd2[NGRAPH * 64];

// ---------------- packed f32x2 helpers --------------------------------------
__device__ __forceinline__ unsigned long long ffma2(unsigned long long a,
                                                    unsigned long long b,
                                                    unsigned long long c) {
    unsigned long long d;
    asm("fma.rn.f32x2 %0, %1, %2, %3;" : "=l"(d) : "l"(a), "l"(b), "l"(c));
    return d;
}
__device__ __forceinline__ unsigned long long pack2(float x) {
    unsigned long long d;
    asm("mov.b64 %0, {%1, %1};" : "=l"(d) : "f"(x));
    return d;
}

// ---------------- K-1: detect int32 vs int64 for index inputs ----------------
// If a buffer holds int64 values < 2^31, its odd int32 words (LE high words)
// are ALL zero. If it holds real int32 data, those positions are actual
// indices / batch ids and are nonzero with overwhelming probability.
// All probes stay within the int32-interpretation footprint (no OOB either way).
__global__ void k_detect(const int* ei32, const int* bt32, int E, int Nn) {
    __shared__ int s_ei, s_bt;
    int t = threadIdx.x;                 // 256 threads
    if (t == 0) { s_ei = 0; s_bt = 0; }
    __syncthreads();
    int nz = 0;
    for (int i = t; i < 256; i += 256) nz |= ei32[2 * i + 1];   // < 512 ints < 2E
    if (nz) atomicOr(&s_ei, 1);
    nz = 0;
    int lim = Nn / 2 < 16384 ? Nn / 2 : 16384;                  // < Nn ints
    for (int i = t; i < lim; i += 256) nz |= bt32[2 * i + 1];
    if (nz) atomicOr(&s_bt, 1);
    __syncthreads();
    if (t == 0) {
        g_is64_ei = s_ei ? 0 : 1;
        g_is64_bt = s_bt ? 0 : 1;
    }
}

// ---------------- K0: zero histogram ----------------------------------------
__global__ void k_init() {
    int t = threadIdx.x;
    if (t < NGRAPH) g_hist[t] = 0;
}

// ---------------- K1: seg = batch[col], int32 copies, histogram -------------
__global__ void k_seg(const void* __restrict__ ei_raw,
                      const void* __restrict__ bt_raw, int E, int Nn) {
    __shared__ int sh[NGRAPH];
    int t = threadIdx.x;
    if (t < NGRAPH) sh[t] = 0;
    __syncthreads();
    int e = blockIdx.x * blockDim.x + t;
    if (e < E) {
        bool e64 = (g_is64_ei != 0);
        bool b64 = (g_is64_bt != 0);
        int ci, ri;
        if (e64) {
            ci = (int)((const long long*)ei_raw)[e];
            ri = (int)((const long long*)ei_raw)[(size_t)E + e];
        } else {
            ci = ((const int*)ei_raw)[e];
            ri = ((const int*)ei_raw)[E + e];
        }
        ci = min(max(ci, 0), Nn - 1);
        ri = min(max(ri, 0), Nn - 1);
        int s = b64 ? (int)((const long long*)bt_raw)[ci]
                    : ((const int*)bt_raw)[ci];
        s = min(max(s, 0), NGRAPH - 1);
        g_col[e] = ci; g_row[e] = ri; g_seg[e] = s;
        atomicAdd(&sh[s], 1);
    }
    __syncthreads();
    if (t < NGRAPH && sh[t]) atomicAdd(&g_hist[t], sh[t]);
}

// ---------------- K2: prefix scan over 128 bins ------------------------------
__global__ void k_scan() {
    __shared__ int sc[NGRAPH];
    int t = threadIdx.x;  // blockDim == 128
    int v = g_hist[t];
    sc[t] = v;
    __syncthreads();
    for (int d = 1; d < NGRAPH; d <<= 1) {
        int add = (t >= d) ? sc[t - d] : 0;
        __syncthreads();
        sc[t] += add;
        __syncthreads();
    }
    int incl = sc[t];
    g_off[t + 1] = incl;
    g_cursor[t]  = incl - v;   // exclusive prefix
    if (t == 0) g_off[0] = 0;
}

// ---------------- K3: scatter edges into segment-sorted order ----------------
__global__ void k_scatter(int E) {
    int e = blockIdx.x * blockDim.x + threadIdx.x;
    if (e >= E) return;
    int s   = g_seg[e];
    int pos = atomicAdd(&g_cursor[s], 1);
    g_perm[pos] = e;
    g_segS[pos] = s;
    g_colS[pos] = g_col[e];
    g_rowS[pos] = g_row[e];
}

// ---------------- K4: P/Q = emb @ W1-half  (M=N nodes, K=64, N=256) ---------
// BM=128, BN=64, 128 threads, 8x8 micro-tile (rows strided by 16), f32x2 FMA.
__global__ void k_pq(const float* __restrict__ emb,
                     const float* __restrict__ W1, int Nn) {
    __shared__ __align__(16) float Xs[128 * 34];
    __shared__ __align__(16) float Ws[32 * 64];
    int tid = threadIdx.x;
    int m0  = blockIdx.x * 128;
    int nb  = blockIdx.y * 64;
    int z   = blockIdx.z;            // 0 -> P (W1 rows 0..63), 1 -> Q (64..127)
    int r16 = tid >> 3;              // 0..15
    int c8  = tid & 7;               // 0..7
    int cb  = c8 * 8;

    unsigned long long acc[8][4];
#pragma unroll
    for (int i = 0; i < 8; i++)
#pragma unroll
        for (int j = 0; j < 4; j++) acc[i][j] = 0ULL;

    for (int kc = 0; kc < 2; kc++) {
#pragma unroll
        for (int t = tid; t < 128 * 8; t += 128) {
            int rr = t >> 3, q = t & 7;
            int node = m0 + rr; if (node >= Nn) node = Nn - 1;
            float4 v = *(const float4*)&emb[node * 64 + kc * 32 + q * 4];
            float* d = &Xs[rr * 34 + q * 4];
            *(float2*)&d[0] = make_float2(v.x, v.y);
            *(float2*)&d[2] = make_float2(v.z, v.w);
        }
#pragma unroll
        for (int t = tid; t < 512; t += 128) {
            int k = t >> 4, q = t & 15;
            *(float4*)&Ws[k * 64 + q * 4] =
                *(const float4*)&W1[(z * 64 + kc * 32 + k) * 256 + nb + q * 4];
        }
        __syncthreads();
#pragma unroll
        for (int k = 0; k < 32; k++) {
            unsigned long long b0 = *(const unsigned long long*)&Ws[k * 64 + cb + 0];
            unsigned long long b1 = *(const unsigned long long*)&Ws[k * 64 + cb + 2];
            unsigned long long b2 = *(const unsigned long long*)&Ws[k * 64 + cb + 4];
            unsigned long long b3 = *(const unsigned long long*)&Ws[k * 64 + cb + 6];
#pragma unroll
            for (int i = 0; i < 8; i++) {
                unsigned long long pa = pack2(Xs[(r16 + 16 * i) * 34 + k]);
                acc[i][0] = ffma2(pa, b0, acc[i][0]);
                acc[i][1] = ffma2(pa, b1, acc[i][1]);
                acc[i][2] = ffma2(pa, b2, acc[i][2]);
                acc[i][3] = ffma2(pa, b3, acc[i][3]);
            }
        }
        __syncthreads();
    }
    float* dst = z ? g_Q : g_P;
#pragma unroll
    for (int i = 0; i < 8; i++) {
        int node = m0 + r16 + 16 * i;
        if (node < Nn) {
            float* o = &dst[node * 256 + nb + cb];
            *(unsigned long long*)&o[0] = acc[i][0];
            *(unsigned long long*)&o[2] = acc[i][1];
            *(unsigned long long*)&o[4] = acc[i][2];
            *(unsigned long long*)&o[6] = acc[i][3];
        }
    }
}

// ---------------- K5: per-(graph, 32-channel) stats of h1 = P[c]+Q[r] -------
__global__ void k_stats1() {
    int g  = blockIdx.x;
    int c0 = blockIdx.y * 32;
    int lane = threadIdx.x & 31, w = threadIdx.x >> 5;   // 8 warps
    int start = g_off[g], end = g_off[g + 1];
    int ch = c0 + lane;
    float s1 = 0.f, s2 = 0.f;
    for (int m = start + w; m < end; m += 8) {
        float v = g_P[g_colS[m] * 256 + ch] + g_Q[g_rowS[m] * 256 + ch];
        s1 += v; s2 += v * v;
    }
    __shared__ float a1[8][32], a2[8][32];
    a1[w][lane] = s1; a2[w][lane] = s2;
    __syncthreads();
    if (w == 0) {
#pragma unroll
        for (int t = 1; t < 8; t++) { s1 += a1[t][lane]; s2 += a2[t][lane]; }
        int cnti = end - start; if (cnti < 1) cnti = 1;
        float cnt  = (float)cnti;
        float mean = s1 / cnt;
        float var  = fmaxf(s2 / cnt - mean * mean, 0.f);
        g_mean1[g * 256 + ch] = mean;
        g_rstd1[g * 256 + ch] = rsqrtf(var + EPS);
    }
}

// ---------------- K6: h2 = relu(norm1(P[c]+Q[r])) @ W2  (K=256, N=64) -------
__global__ void k_gemm2(const float* __restrict__ W2, int E) {
    __shared__ __align__(16) float Xs[128 * 34];
    __shared__ __align__(16) float Ws[32 * 64];
    __shared__ int cS[128], rS[128], sS[128];
    int tid = threadIdx.x;
    int m0  = blockIdx.x * 128;
    if (tid < 128) {
        int m = m0 + tid; if (m >= E) m = E - 1;
        cS[tid] = g_colS[m]; rS[tid] = g_rowS[m]; sS[tid] = g_segS[m];
    }
    __syncthreads();
    int r16 = tid >> 3, c8 = tid & 7, cb = c8 * 8;

    unsigned long long acc[8][4];
#pragma unroll
    for (int i = 0; i < 8; i++)
#pragma unroll
        for (int j = 0; j < 4; j++) acc[i][j] = 0ULL;

    for (int kc = 0; kc < 8; kc++) {
#pragma unroll
        for (int t = tid; t < 128 * 8; t += 128) {
            int rr = t >> 3, q = t & 7;
            int ko = kc * 32 + q * 4;
            int c = cS[rr], r = rS[rr], s = sS[rr];
            float4 p  = *(const float4*)&g_P[c * 256 + ko];
            float4 qv = *(const float4*)&g_Q[r * 256 + ko];
            float4 mu = *(const float4*)&g_mean1[s * 256 + ko];
            float4 rs = *(const float4*)&g_rstd1[s * 256 + ko];
            float* d = &Xs[rr * 34 + q * 4];
            d[0] = fmaxf((p.x + qv.x - mu.x) * rs.x, 0.f);
            d[1] = fmaxf((p.y + qv.y - mu.y) * rs.y, 0.f);
            d[2] = fmaxf((p.z + qv.z - mu.z) * rs.z, 0.f);
            d[3] = fmaxf((p.w + qv.w - mu.w) * rs.w, 0.f);
        }
#pragma unroll
        for (int t = tid; t < 512; t += 128) {
            int k = t >> 4, q = t & 15;
            *(float4*)&Ws[k * 64 + q * 4] =
                *(const float4*)&W2[(kc * 32 + k) * 64 + q * 4];
        }
        __syncthreads();
#pragma unroll
        for (int k = 0; k < 32; k++) {
            unsigned long long b0 = *(const unsigned long long*)&Ws[k * 64 + cb + 0];
            unsigned long long b1 = *(const unsigned long long*)&Ws[k * 64 + cb + 2];
            unsigned long long b2 = *(const unsigned long long*)&Ws[k * 64 + cb + 4];
            unsigned long long b3 = *(const unsigned long long*)&Ws[k * 64 + cb + 6];
#pragma unroll
            for (int i = 0; i < 8; i++) {
                unsigned long long pa = pack2(Xs[(r16 + 16 * i) * 34 + k]);
                acc[i][0] = ffma2(pa, b0, acc[i][0]);
                acc[i][1] = ffma2(pa, b1, acc[i][1]);
                acc[i][2] = ffma2(pa, b2, acc[i][2]);
                acc[i][3] = ffma2(pa, b3, acc[i][3]);
            }
        }
        __syncthreads();
    }
#pragma unroll
    for (int i = 0; i < 8; i++) {
        int m = m0 + r16 + 16 * i;
        if (m < E) {
            float* o = &g_h2[(size_t)m * 64 + cb];
            *(unsigned long long*)&o[0] = acc[i][0];
            *(unsigned long long*)&o[2] = acc[i][1];
            *(unsigned long long*)&o[4] = acc[i][2];
            *(unsigned long long*)&o[6] = acc[i][3];
        }
    }
}

// ---------------- K7: stats of h2 -------------------------------------------
__global__ void k_stats2() {
    int g  = blockIdx.x;
    int c0 = blockIdx.y * 32;
    int lane = threadIdx.x & 31, w = threadIdx.x >> 5;
    int start = g_off[g], end = g_off[g + 1];
    int ch = c0 + lane;
    float s1 = 0.f, s2 = 0.f;
    for (int m = start + w; m < end; m += 8) {
        float v = g_h2[(size_t)m * 64 + ch];
        s1 += v; s2 += v * v;
    }
    __shared__ float a1[8][32], a2[8][32];
    a1[w][lane] = s1; a2[w][lane] = s2;
    __syncthreads();
    if (w == 0) {
#pragma unroll
        for (int t = 1; t < 8; t++) { s1 += a1[t][lane]; s2 += a2[t][lane]; }
        int cnti = end - start; if (cnti < 1) cnti = 1;
        float cnt  = (float)cnti;
        float mean = s1 / cnt;
        float var  = fmaxf(s2 / cnt - mean * mean, 0.f);
        g_mean2[g * 64 + ch] = mean;
        g_rstd2[g * 64 + ch] = rsqrtf(var + EPS);
    }
}

// ---------------- K8: out[perm[m]] = relu(norm2(h2)) . W3 + b3 --------------
__global__ void k_final(const float* __restrict__ W3,
                        const float* __restrict__ b3,
                        float* __restrict__ out, int E) {
    __shared__ __align__(16) float sm[128 * 65];
    __shared__ float w3s[64];
    __shared__ int   sS[128];
    int tid = threadIdx.x;   // blockDim == 128
    int m0  = blockIdx.x * 128;
    if (tid < 64) w3s[tid] = W3[tid];
    {
        int m = m0 + tid; if (m >= E) m = E - 1;
        sS[tid] = g_segS[m];
    }
    __syncthreads();
#pragma unroll
    for (int t = tid; t < 128 * 16; t += 128) {
        int rr = t >> 4, q = t & 15;
        int m = m0 + rr; if (m >= E) m = E - 1;
        float4 v  = *(const float4*)&g_h2[(size_t)m * 64 + q * 4];
        int s = sS[rr];
        float4 mu = *(const float4*)&g_mean2[s * 64 + q * 4];
        float4 rs = *(const float4*)&g_rstd2[s * 64 + q * 4];
        float* d = &sm[rr * 65 + q * 4];
        d[0] = fmaxf((v.x - mu.x) * rs.x, 0.f);
        d[1] = fmaxf((v.y - mu.y) * rs.y, 0.f);
        d[2] = fmaxf((v.z - mu.z) * rs.z, 0.f);
        d[3] = fmaxf((v.w - mu.w) * rs.w, 0.f);
    }
    __syncthreads();
    int m = m0 + tid;
    if (m < E) {
        float acc = 0.f;
#pragma unroll
        for (int k = 0; k < 64; k++) acc += sm[tid * 65 + k] * w3s[k];
        out[g_perm[m]] = acc + b3[0];
    }
}

// ---------------- launch ------------------------------------------------------
extern "C" void kernel_launch(void* const* d_in, const int* in_sizes, int n_in,
                              void* d_out, int out_size) {
    const float* emb = (const float*)d_in[0];
    const void*  ei  = d_in[1];
    const void*  bt  = d_in[2];
    const float* W1  = (const float*)d_in[3];
    // d_in[4] = b1 : cancels exactly through affine-free InstanceNorm
    const float* W2  = (const float*)d_in[5];
    // d_in[6] = b2 : cancels exactly through affine-free InstanceNorm
    const float* W3  = (const float*)d_in[7];
    const float* b3  = (const float*)d_in[8];
    float* out = (float*)d_out;

    int Nn = in_sizes[0] / 64;
    int E  = in_sizes[1] / 2;

    k_detect<<<1, 256>>>((const int*)ei, (const int*)bt, E, Nn);
    k_init<<<1, 128>>>();
    k_seg<<<(E + 255) / 256, 256>>>(ei, bt, E, Nn);
    k_scan<<<1, 128>>>();
    k_scatter<<<(E + 255) / 256, 256>>>(E);

    dim3 gPQ((Nn + 127) / 128, 4, 2);
    k_pq<<<gPQ, 128>>>(emb, W1, Nn);

    k_stats1<<<dim3(128, 8), 256>>>();
    k_gemm2<<<(E + 127) / 128, 128>>>(W2, E);
    k_stats2<<<dim3(128, 2), 256>>>();
    k_final<<<(E + 127) / 128, 128>>>(W3, b3, out, E);
}

// round 4
// speedup vs baseline: 1.0135x; 1.0135x over previous
#include <cuda_runtime.h>
#include <cstdint>

#define EPS 1e-5f
#define NGRAPH 128
#define EMAX 800000
#define NMAX 50000

// ---------------- scratch (__device__ globals; no allocation allowed) -------
__device__ int g_is64_ei, g_is64_bt;
__device__ int g_nodeCnt[NMAX];
__device__ int g_nodeOff[NMAX];
__device__ int g_cursorN[NMAX];
__device__ int g_off[NGRAPH + 1];
__device__ int g_col[EMAX];
__device__ int g_row[EMAX];
__device__ int g_perm[EMAX];
__device__ int g_segS[EMAX];
__device__ int g_colS[EMAX];
__device__ int g_rowS[EMAX];
__device__ __align__(16) float g_P[NMAX * 256];   // emb @ W1[:64 ,:]
__device__ __align__(16) float g_Q[NMAX * 256];   // emb @ W1[64:,:]
__device__ __align__(16) float g_h2[(size_t)EMAX * 64];
__device__ __align__(16) float g_mean1[NGRAPH * 256];
__device__ __align__(16) float g_rstd1[NGRAPH * 256];
__device__ __align__(16) float g_mean2[NGRAPH * 64];
__device__ __align__(16) float g_rstd2[NGRAPH * 64];

// ---------------- packed f32x2 helpers --------------------------------------
__device__ __forceinline__ unsigned long long ffma2(unsigned long long a,
                                                    unsigned long long b,
                                                    unsigned long long c) {
    unsigned long long d;
    asm("fma.rn.f32x2 %0, %1, %2, %3;" : "=l"(d) : "l"(a), "l"(b), "l"(c));
    return d;
}
__device__ __forceinline__ unsigned long long pack2(float x) {
    unsigned long long d;
    asm("mov.b64 %0, {%1, %1};" : "=l"(d) : "f"(x));
    return d;
}

// ---------------- K4: P/Q = emb @ W1-half  (M=N nodes, K=64, N=256) ---------
__global__ void k_pq(const float* __restrict__ emb,
                     const float* __restrict__ W1, int Nn) {
    __shared__ __align__(16) float Xs[128 * 34];
    __shared__ __align__(16) float Ws[32 * 64];
    int tid = threadIdx.x;
    int m0  = blockIdx.x * 128;
    int nb  = blockIdx.y * 64;
    int z   = blockIdx.z;            // 0 -> P, 1 -> Q
    int r16 = tid >> 3;
    int cb  = (tid & 7) * 8;

    unsigned long long acc[8][4];
#pragma unroll
    for (int i = 0; i < 8; i++)
#pragma unroll
        for (int j = 0; j < 4; j++) acc[i][j] = 0ULL;

    for (int kc = 0; kc < 2; kc++) {
#pragma unroll
        for (int t = tid; t < 128 * 8; t += 128) {
            int rr = t >> 3, q = t & 7;
            int node = m0 + rr; if (node >= Nn) node = Nn - 1;
            float4 v = *(const float4*)&emb[node * 64 + kc * 32 + q * 4];
            float* d = &Xs[rr * 34 + q * 4];
            *(float2*)&d[0] = make_float2(v.x, v.y);
            *(float2*)&d[2] = make_float2(v.z, v.w);
        }
#pragma unroll
        for (int t = tid; t < 512; t += 128) {
            int k = t >> 4, q = t & 15;
            *(float4*)&Ws[k * 64 + q * 4] =
                *(const float4*)&W1[(z * 64 + kc * 32 + k) * 256 + nb + q * 4];
        }
        __syncthreads();
#pragma unroll
        for (int k = 0; k < 32; k++) {
            ulonglong2 bA = *(const ulonglong2*)&Ws[k * 64 + cb + 0];
            ulonglong2 bB = *(const ulonglong2*)&Ws[k * 64 + cb + 4];
#pragma unroll
            for (int i = 0; i < 8; i++) {
                unsigned long long pa = pack2(Xs[(r16 + 16 * i) * 34 + k]);
                acc[i][0] = ffma2(pa, bA.x, acc[i][0]);
                acc[i][1] = ffma2(pa, bA.y, acc[i][1]);
                acc[i][2] = ffma2(pa, bB.x, acc[i][2]);
                acc[i][3] = ffma2(pa, bB.y, acc[i][3]);
            }
        }
        __syncthreads();
    }
    float* dst = z ? g_Q : g_P;
#pragma unroll
    for (int i = 0; i < 8; i++) {
        int node = m0 + r16 + 16 * i;
        if (node < Nn) {
            float* o = &dst[node * 256 + nb + cb];
            *(unsigned long long*)&o[0] = acc[i][0];
            *(unsigned long long*)&o[2] = acc[i][1];
            *(unsigned long long*)&o[4] = acc[i][2];
            *(unsigned long long*)&o[6] = acc[i][3];
        }
    }
}

// ---------------- K: dtype detect + zero node histogram ----------------------
__global__ void k_detect(const int* ei32, const int* bt32, int E, int Nn) {
    __shared__ int s_ei, s_bt;
    int t = threadIdx.x;               // 256 threads, 1 block
    if (t == 0) { s_ei = 0; s_bt = 0; }
    __syncthreads();
    int nz = 0;
    for (int i = t; i < 256; i += 256) nz |= ei32[2 * i + 1];
    if (nz) atomicOr(&s_ei, 1);
    nz = 0;
    int lim = Nn / 2 < 16384 ? Nn / 2 : 16384;
    for (int i = t; i < lim; i += 256) nz |= bt32[2 * i + 1];
    if (nz) atomicOr(&s_bt, 1);
    for (int i = t; i < NMAX; i += 256) g_nodeCnt[i] = 0;
    __syncthreads();
    if (t == 0) { g_is64_ei = s_ei ? 0 : 1; g_is64_bt = s_bt ? 0 : 1; }
}

// ---------------- K: decode edges + node histogram ---------------------------
__global__ void k_edges(const void* __restrict__ ei_raw, int E, int Nn) {
    int e = blockIdx.x * blockDim.x + threadIdx.x;
    if (e >= E) return;
    bool e64 = (g_is64_ei != 0);
    int ci, ri;
    if (e64) {
        ci = (int)((const long long*)ei_raw)[e];
        ri = (int)((const long long*)ei_raw)[(size_t)E + e];
    } else {
        ci = ((const int*)ei_raw)[e];
        ri = ((const int*)ei_raw)[E + e];
    }
    ci = min(max(ci, 0), Nn - 1);
    ri = min(max(ri, 0), Nn - 1);
    g_col[e] = ci; g_row[e] = ri;
    atomicAdd(&g_nodeCnt[ci], 1);
}

// ---------------- K: single-block scan of node counts + graph offsets --------
__global__ void k_scan_node(const void* __restrict__ bt_raw, int E, int Nn) {
    __shared__ int s[1024];
    int t = threadIdx.x;               // 1024 threads, 1 block
    int chunk = (Nn + 1023) >> 10;
    int b0 = t * chunk, b1 = min(b0 + chunk, Nn);
    int sum = 0;
    for (int i = b0; i < b1; i++) sum += g_nodeCnt[i];
    s[t] = sum;
    __syncthreads();
    for (int d = 1; d < 1024; d <<= 1) {
        int v = (t >= d) ? s[t - d] : 0;
        __syncthreads();
        s[t] += v;
        __syncthreads();
    }
    int run = s[t] - sum;              // exclusive prefix
    for (int i = b0; i < b1; i++) {
        int c = g_nodeCnt[i];
        g_nodeOff[i] = run;
        g_cursorN[i] = run;
        run += c;
    }
    __syncthreads();
    // graph offsets: batch is sorted, so col-sorted edges are graph-sorted.
    if (t < NGRAPH) {
        bool b64 = (g_is64_bt != 0);
        int lo = 0, hi = Nn;
        while (lo < hi) {
            int mid = (lo + hi) >> 1;
            long long bv = b64 ? ((const long long*)bt_raw)[mid]
                               : (long long)((const int*)bt_raw)[mid];
            if (bv < (long long)t) lo = mid + 1; else hi = mid;
        }
        g_off[t] = (lo < Nn) ? g_nodeOff[lo] : E;
    }
    if (t == 0) g_off[NGRAPH] = E;
}

// ---------------- K: scatter edges into col-sorted order ---------------------
__global__ void k_scatter(const void* __restrict__ bt_raw, int E) {
    int e = blockIdx.x * blockDim.x + threadIdx.x;
    if (e >= E) return;
    int ci = g_col[e];
    int pos = atomicAdd(&g_cursorN[ci], 1);
    bool b64 = (g_is64_bt != 0);
    int sg = b64 ? (int)((const long long*)bt_raw)[ci]
                 : ((const int*)bt_raw)[ci];
    sg = min(max(sg, 0), NGRAPH - 1);
    g_perm[pos] = e;
    g_colS[pos] = ci;
    g_rowS[pos] = g_row[e];
    g_segS[pos] = sg;
}

// ---------------- K5: per-(graph, 32-channel) stats of h1 = P[c]+Q[r] -------
__global__ void k_stats1() {
    int g  = blockIdx.x;
    int c0 = blockIdx.y * 32;
    int lane = threadIdx.x & 31, w = threadIdx.x >> 5;   // 8 warps
    int start = g_off[g], end = g_off[g + 1];
    int ch = c0 + lane;
    float s1 = 0.f, s2 = 0.f;
    for (int m = start + w; m < end; m += 8) {
        float v = g_P[g_colS[m] * 256 + ch] + g_Q[g_rowS[m] * 256 + ch];
        s1 += v; s2 += v * v;
    }
    __shared__ float a1[8][32], a2[8][32];
    a1[w][lane] = s1; a2[w][lane] = s2;
    __syncthreads();
    if (w == 0) {
#pragma unroll
        for (int t = 1; t < 8; t++) { s1 += a1[t][lane]; s2 += a2[t][lane]; }
        int cnti = end - start; if (cnti < 1) cnti = 1;
        float cnt  = (float)cnti;
        float mean = s1 / cnt;
        float var  = fmaxf(s2 / cnt - mean * mean, 0.f);
        g_mean1[g * 256 + ch] = mean;
        g_rstd1[g * 256 + ch] = rsqrtf(var + EPS);
    }
}

// ---------------- K6: h2 = relu(norm1(P[c]+Q[r])) @ W2  (K=256, N=64) -------
__global__ void k_gemm2(const float* __restrict__ W2, int E) {
    __shared__ __align__(16) float Xs[128 * 34];
    __shared__ __align__(16) float Ws[32 * 64];
    __shared__ int cS[128], rS[128], sS[128];
    int tid = threadIdx.x;
    int m0  = blockIdx.x * 128;
    if (tid < 128) {
        int m = m0 + tid; if (m >= E) m = E - 1;
        cS[tid] = g_colS[m]; rS[tid] = g_rowS[m]; sS[tid] = g_segS[m];
    }
    __syncthreads();
    int r16 = tid >> 3, cb = (tid & 7) * 8;

    unsigned long long acc[8][4];
#pragma unroll
    for (int i = 0; i < 8; i++)
#pragma unroll
        for (int j = 0; j < 4; j++) acc[i][j] = 0ULL;

    for (int kc = 0; kc < 8; kc++) {
#pragma unroll
        for (int t = tid; t < 128 * 8; t += 128) {
            int rr = t >> 3, q = t & 7;
            int ko = kc * 32 + q * 4;
            int c = cS[rr], r = rS[rr], s = sS[rr];
            float4 p  = *(const float4*)&g_P[c * 256 + ko];
            float4 qv = *(const float4*)&g_Q[r * 256 + ko];
            float4 mu = *(const float4*)&g_mean1[s * 256 + ko];
            float4 rs = *(const float4*)&g_rstd1[s * 256 + ko];
            float* d = &Xs[rr * 34 + q * 4];
            d[0] = fmaxf((p.x + qv.x - mu.x) * rs.x, 0.f);
            d[1] = fmaxf((p.y + qv.y - mu.y) * rs.y, 0.f);
            d[2] = fmaxf((p.z + qv.z - mu.z) * rs.z, 0.f);
            d[3] = fmaxf((p.w + qv.w - mu.w) * rs.w, 0.f);
        }
#pragma unroll
        for (int t = tid; t < 512; t += 128) {
            int k = t >> 4, q = t & 15;
            *(float4*)&Ws[k * 64 + q * 4] =
                *(const float4*)&W2[(kc * 32 + k) * 64 + q * 4];
        }
        __syncthreads();
#pragma unroll
        for (int k = 0; k < 32; k++) {
            ulonglong2 bA = *(const ulonglong2*)&Ws[k * 64 + cb + 0];
            ulonglong2 bB = *(const ulonglong2*)&Ws[k * 64 + cb + 4];
#pragma unroll
            for (int i = 0; i < 8; i++) {
                unsigned long long pa = pack2(Xs[(r16 + 16 * i) * 34 + k]);
                acc[i][0] = ffma2(pa, bA.x, acc[i][0]);
                acc[i][1] = ffma2(pa, bA.y, acc[i][1]);
                acc[i][2] = ffma2(pa, bB.x, acc[i][2]);
                acc[i][3] = ffma2(pa, bB.y, acc[i][3]);
            }
        }
        __syncthreads();
    }
#pragma unroll
    for (int i = 0; i < 8; i++) {
        int m = m0 + r16 + 16 * i;
        if (m < E) {
            float* o = &g_h2[(size_t)m * 64 + cb];
            *(unsigned long long*)&o[0] = acc[i][0];
            *(unsigned long long*)&o[2] = acc[i][1];
            *(unsigned long long*)&o[4] = acc[i][2];
            *(unsigned long long*)&o[6] = acc[i][3];
        }
    }
}

// ---------------- K7: stats of h2 --------------------------------------------
__global__ void k_stats2() {
    int g  = blockIdx.x;
    int c0 = blockIdx.y * 32;
    int lane = threadIdx.x & 31, w = threadIdx.x >> 5;
    int start = g_off[g], end = g_off[g + 1];
    int ch = c0 + lane;
    float s1 = 0.f, s2 = 0.f;
    for (int m = start + w; m < end; m += 8) {
        float v = g_h2[(size_t)m * 64 + ch];
        s1 += v; s2 += v * v;
    }
    __shared__ float a1[8][32], a2[8][32];
    a1[w][lane] = s1; a2[w][lane] = s2;
    __syncthreads();
    if (w == 0) {
#pragma unroll
        for (int t = 1; t < 8; t++) { s1 += a1[t][lane]; s2 += a2[t][lane]; }
        int cnti = end - start; if (cnti < 1) cnti = 1;
        float cnt  = (float)cnti;
        float mean = s1 / cnt;
        float var  = fmaxf(s2 / cnt - mean * mean, 0.f);
        g_mean2[g * 64 + ch] = mean;
        g_rstd2[g * 64 + ch] = rsqrtf(var + EPS);
    }
}

// ---------------- K8: out[perm[m]] = relu(norm2(h2)) . W3 + b3 ---------------
__global__ void k_final(const float* __restrict__ W3,
                        const float* __restrict__ b3,
                        float* __restrict__ out, int E) {
    __shared__ __align__(16) float sm[128 * 65];
    __shared__ float w3s[64];
    __shared__ int   sS[128];
    int tid = threadIdx.x;   // blockDim == 128
    int m0  = blockIdx.x * 128;
    if (tid < 64) w3s[tid] = W3[tid];
    {
        int m = m0 + tid; if (m >= E) m = E - 1;
        sS[tid] = g_segS[m];
    }
    __syncthreads();
#pragma unroll
    for (int t = tid; t < 128 * 16; t += 128) {
        int rr = t >> 4, q = t & 15;
        int m = m0 + rr; if (m >= E) m = E - 1;
        float4 v  = *(const float4*)&g_h2[(size_t)m * 64 + q * 4];
        int s = sS[rr];
        float4 mu = *(const float4*)&g_mean2[s * 64 + q * 4];
        float4 rs = *(const float4*)&g_rstd2[s * 64 + q * 4];
        float* d = &sm[rr * 65 + q * 4];
        d[0] = fmaxf((v.x - mu.x) * rs.x, 0.f);
        d[1] = fmaxf((v.y - mu.y) * rs.y, 0.f);
        d[2] = fmaxf((v.z - mu.z) * rs.z, 0.f);
        d[3] = fmaxf((v.w - mu.w) * rs.w, 0.f);
    }
    __syncthreads();
    int m = m0 + tid;
    if (m < E) {
        float acc = 0.f;
#pragma unroll
        for (int k = 0; k < 64; k++) acc += sm[tid * 65 + k] * w3s[k];
        out[g_perm[m]] = acc + b3[0];
    }
}

// ---------------- launch -------------------------------------------------------
extern "C" void kernel_launch(void* const* d_in, const int* in_sizes, int n_in,
                              void* d_out, int out_size) {
    const float* emb = (const float*)d_in[0];
    const void*  ei  = d_in[1];
    const void*  bt  = d_in[2];
    const float* W1  = (const float*)d_in[3];
    // d_in[4] = b1 : cancels exactly through affine-free InstanceNorm
    const float* W2  = (const float*)d_in[5];
    // d_in[6] = b2 : cancels exactly through affine-free InstanceNorm
    const float* W3  = (const float*)d_in[7];
    const float* b3  = (const float*)d_in[8];
    float* out = (float*)d_out;

    int Nn = in_sizes[0] / 64;
    int E  = in_sizes[1] / 2;

    // k_pq first: independent of edge preprocessing (also aligns ncu -s 5
    // onto k_stats1).
    dim3 gPQ((Nn + 127) / 128, 4, 2);
    k_pq<<<gPQ, 128>>>(emb, W1, Nn);

    k_detect<<<1, 256>>>((const int*)ei, (const int*)bt, E, Nn);
    k_edges<<<(E + 255) / 256, 256>>>(ei, E, Nn);
    k_scan_node<<<1, 1024>>>(bt, E, Nn);
    k_scatter<<<(E + 255) / 256, 256>>>(bt, E);

    k_stats1<<<dim3(128, 8), 256>>>();
    k_gemm2<<<(E + 127) / 128, 128>>>(W2, E);
    k_stats2<<<dim3(128, 2), 256>>>();
    k_final<<<(E + 127) / 128, 128>>>(W3, b3, out, E);
}

// round 5
// speedup vs baseline: 1.4206x; 1.4017x over previous
#include <cuda_runtime.h>
#include <cuda_bf16.h>
#include <cstdint>

#define EPS 1e-5f
#define NGRAPH 128
#define EMAX 800000
#define NMAX 50000

// ---------------- scratch (__device__ globals; no allocation allowed) -------
__device__ int g_is64_bt;
__device__ int g_nodeCnt[NMAX];
__device__ int g_nodeOff[NMAX];
__device__ int g_cursorN[NMAX];
__device__ int g_off[NGRAPH + 1];
__device__ int g_col[EMAX];
__device__ int g_row[EMAX];
__device__ int g_perm[EMAX];
__device__ int g_segS[EMAX];
__device__ int g_colS[EMAX];
__device__ int g_rowS[EMAX];
__device__ __align__(16) float g_P[NMAX * 256];   // emb @ W1[:64 ,:]
__device__ __align__(16) float g_Q[NMAX * 256];   // emb @ W1[64:,:]
__device__ __align__(16) float g_h2[(size_t)EMAX * 64];
__device__ __align__(16) float g_mean1[NGRAPH * 256];
__device__ __align__(16) float g_rstd1[NGRAPH * 256];
__device__ __align__(16) float g_mean2[NGRAPH * 64];
__device__ __align__(16) float g_rstd2[NGRAPH * 64];

// ---------------- helpers ----------------------------------------------------
__device__ __forceinline__ unsigned long long ffma2(unsigned long long a,
                                                    unsigned long long b,
                                                    unsigned long long c) {
    unsigned long long d;
    asm("fma.rn.f32x2 %0, %1, %2, %3;" : "=l"(d) : "l"(a), "l"(b), "l"(c));
    return d;
}
__device__ __forceinline__ unsigned long long pack2(float x) {
    unsigned long long d;
    asm("mov.b64 %0, {%1, %1};" : "=l"(d) : "f"(x));
    return d;
}
__device__ __forceinline__ uint32_t pkbf(float a, float b) {
    __nv_bfloat162 h = __floats2bfloat162_rn(a, b);
    return *(uint32_t*)&h;
}
// split v into bf16 hi + bf16 lo (v ~= hi + lo)
__device__ __forceinline__ void bsplit(float v, float& hi, float& lo) {
    __nv_bfloat16 h = __float2bfloat16(v);
    hi = __bfloat162float(h);
    lo = v - hi;
}
__device__ __forceinline__ void mma16816(float* c, uint32_t a0, uint32_t a1,
                                         uint32_t a2, uint32_t a3,
                                         uint32_t b0, uint32_t b1) {
    asm volatile(
        "mma.sync.aligned.m16n8k16.row.col.f32.bf16.bf16.f32 "
        "{%0,%1,%2,%3}, {%4,%5,%6,%7}, {%8,%9}, {%0,%1,%2,%3};"
        : "+f"(c[0]), "+f"(c[1]), "+f"(c[2]), "+f"(c[3])
        : "r"(a0), "r"(a1), "r"(a2), "r"(a3), "r"(b0), "r"(b1));
}

// ---------------- K1: zero node histogram ------------------------------------
__global__ void k_zero() {
    int i = blockIdx.x * 1024 + threadIdx.x;
    if (i < NMAX) g_nodeCnt[i] = 0;
}

// ---------------- K2: decode edges + node histogram (block-local detect) -----
__global__ void k_edges(const void* __restrict__ ei_raw, int E, int Nn) {
    __shared__ int s_nz;
    int t = threadIdx.x;               // 256
    if (t == 0) s_nz = 0;
    __syncthreads();
    const int* ei32 = (const int*)ei_raw;
    if (ei32[2 * t + 1]) atomicOr(&s_nz, 1);   // 2t+1 < 512 << 2E
    __syncthreads();
    bool e64 = (s_nz == 0);
    int e = blockIdx.x * blockDim.x + t;
    if (e >= E) return;
    int ci, ri;
    if (e64) {
        ci = (int)((const long long*)ei_raw)[e];
        ri = (int)((const long long*)ei_raw)[(size_t)E + e];
    } else {
        ci = ei32[e];
        ri = ei32[E + e];
    }
    ci = min(max(ci, 0), Nn - 1);
    ri = min(max(ri, 0), Nn - 1);
    g_col[e] = ci; g_row[e] = ri;
    atomicAdd(&g_nodeCnt[ci], 1);
}

// ---------------- K3: tile-scan of node counts + graph offsets + bt detect ---
__global__ void k_scan_node(const void* __restrict__ bt_raw, int E, int Nn) {
    __shared__ int warpSum[32];
    __shared__ int s_bt, s_carry;
    int t = threadIdx.x;               // 1024
    int lane = t & 31, w = t >> 5;
    if (t == 0) { s_bt = 0; s_carry = 0; }
    __syncthreads();
    // batch dtype detect (odd int32 words all zero <=> int64)
    {
        const int* bt32 = (const int*)bt_raw;
        int lim = Nn / 2 < 16384 ? Nn / 2 : 16384;
        int nz = 0;
        for (int i = t; i < lim; i += 1024) nz |= bt32[2 * i + 1];
        for (int d = 16; d; d >>= 1) nz |= __shfl_xor_sync(~0u, nz, d);
        if (lane == 0 && nz) atomicOr(&s_bt, 1);
    }
    __syncthreads();
    bool b64 = (s_bt == 0);
    if (t == 0) g_is64_bt = b64 ? 1 : 0;

    int ntile = (Nn + 4095) >> 12;
    for (int tile = 0; tile < ntile; tile++) {
        int idx0 = (tile << 12) + t * 4;
        int c0 = 0, c1 = 0, c2 = 0, c3 = 0;
        if (idx0 + 3 < Nn) {
            int4 c = *(const int4*)&g_nodeCnt[idx0];
            c0 = c.x; c1 = c.y; c2 = c.z; c3 = c.w;
        } else {
            if (idx0 + 0 < Nn) c0 = g_nodeCnt[idx0 + 0];
            if (idx0 + 1 < Nn) c1 = g_nodeCnt[idx0 + 1];
            if (idx0 + 2 < Nn) c2 = g_nodeCnt[idx0 + 2];
            if (idx0 + 3 < Nn) c3 = g_nodeCnt[idx0 + 3];
        }
        int s = c0 + c1 + c2 + c3;
        int v = s;
        for (int d = 1; d < 32; d <<= 1) {
            int u = __shfl_up_sync(~0u, v, d);
            if (lane >= d) v += u;
        }
        if (lane == 31) warpSum[w] = v;
        __syncthreads();
        if (w == 0) {
            int x = warpSum[lane];
            for (int d = 1; d < 32; d <<= 1) {
                int u = __shfl_up_sync(~0u, x, d);
                if (lane >= d) x += u;
            }
            warpSum[lane] = x;
        }
        __syncthreads();
        int warpExcl = w ? warpSum[w - 1] : 0;
        int run = s_carry + warpExcl + (v - s);
        if (idx0 + 0 < Nn) { g_nodeOff[idx0 + 0] = run; g_cursorN[idx0 + 0] = run; run += c0; }
        if (idx0 + 1 < Nn) { g_nodeOff[idx0 + 1] = run; g_cursorN[idx0 + 1] = run; run += c1; }
        if (idx0 + 2 < Nn) { g_nodeOff[idx0 + 2] = run; g_cursorN[idx0 + 2] = run; run += c2; }
        if (idx0 + 3 < Nn) { g_nodeOff[idx0 + 3] = run; g_cursorN[idx0 + 3] = run; run += c3; }
        __syncthreads();
        if (t == 0) s_carry += warpSum[31];
        __syncthreads();
    }
    // graph offsets: batch sorted by node id -> col-sorted edges are graph-sorted
    if (t < NGRAPH) {
        int lo = 0, hi = Nn;
        while (lo < hi) {
            int mid = (lo + hi) >> 1;
            long long bv = b64 ? ((const long long*)bt_raw)[mid]
                               : (long long)((const int*)bt_raw)[mid];
            if (bv < (long long)t) lo = mid + 1; else hi = mid;
        }
        g_off[t] = (lo < Nn) ? g_nodeOff[lo] : E;
    }
    if (t == 0) g_off[NGRAPH] = E;
}

// ---------------- K4: P/Q = emb @ W1-half  (FFMA2; profiled slot) ------------
__global__ void k_pq(const float* __restrict__ emb,
                     const float* __restrict__ W1, int Nn) {
    __shared__ __align__(16) float Xs[128 * 34];
    __shared__ __align__(16) float Ws[32 * 64];
    int tid = threadIdx.x;
    int m0  = blockIdx.x * 128;
    int nb  = blockIdx.y * 64;
    int z   = blockIdx.z;
    int r16 = tid >> 3;
    int cb  = (tid & 7) * 8;

    unsigned long long acc[8][4];
#pragma unroll
    for (int i = 0; i < 8; i++)
#pragma unroll
        for (int j = 0; j < 4; j++) acc[i][j] = 0ULL;

    for (int kc = 0; kc < 2; kc++) {
#pragma unroll
        for (int t = tid; t < 128 * 8; t += 128) {
            int rr = t >> 3, q = t & 7;
            int node = m0 + rr; if (node >= Nn) node = Nn - 1;
            float4 v = *(const float4*)&emb[node * 64 + kc * 32 + q * 4];
            float* d = &Xs[rr * 34 + q * 4];
            *(float2*)&d[0] = make_float2(v.x, v.y);
            *(float2*)&d[2] = make_float2(v.z, v.w);
        }
#pragma unroll
        for (int t = tid; t < 512; t += 128) {
            int k = t >> 4, q = t & 15;
            *(float4*)&Ws[k * 64 + q * 4] =
                *(const float4*)&W1[(z * 64 + kc * 32 + k) * 256 + nb + q * 4];
        }
        __syncthreads();
#pragma unroll
        for (int k = 0; k < 32; k++) {
            ulonglong2 bA = *(const ulonglong2*)&Ws[k * 64 + cb + 0];
            ulonglong2 bB = *(const ulonglong2*)&Ws[k * 64 + cb + 4];
#pragma unroll
            for (int i = 0; i < 8; i++) {
                unsigned long long pa = pack2(Xs[(r16 + 16 * i) * 34 + k]);
                acc[i][0] = ffma2(pa, bA.x, acc[i][0]);
                acc[i][1] = ffma2(pa, bA.y, acc[i][1]);
                acc[i][2] = ffma2(pa, bB.x, acc[i][2]);
                acc[i][3] = ffma2(pa, bB.y, acc[i][3]);
            }
        }
        __syncthreads();
    }
    float* dst = z ? g_Q : g_P;
#pragma unroll
    for (int i = 0; i < 8; i++) {
        int node = m0 + r16 + 16 * i;
        if (node < Nn) {
            float* o = &dst[node * 256 + nb + cb];
            *(unsigned long long*)&o[0] = acc[i][0];
            *(unsigned long long*)&o[2] = acc[i][1];
            *(unsigned long long*)&o[4] = acc[i][2];
            *(unsigned long long*)&o[6] = acc[i][3];
        }
    }
}

// ---------------- K5: scatter edges into col-sorted order --------------------
__global__ void k_scatter(const void* __restrict__ bt_raw, int E) {
    int e = blockIdx.x * blockDim.x + threadIdx.x;
    if (e >= E) return;
    int ci = g_col[e];
    int pos = atomicAdd(&g_cursorN[ci], 1);
    bool b64 = (g_is64_bt != 0);
    int sg = b64 ? (int)((const long long*)bt_raw)[ci]
                 : ((const int*)bt_raw)[ci];
    sg = min(max(sg, 0), NGRAPH - 1);
    g_perm[pos] = e;
    g_colS[pos] = ci;
    g_rowS[pos] = g_row[e];
    g_segS[pos] = sg;
}

// ---------------- K6: per-(graph, 32-channel) stats of h1 = P[c]+Q[r] -------
__global__ void k_stats1() {
    int g  = blockIdx.x;
    int c0 = blockIdx.y * 32;
    int lane = threadIdx.x & 31, w = threadIdx.x >> 5;   // 8 warps
    int start = g_off[g], end = g_off[g + 1];
    int ch = c0 + lane;
    float s1 = 0.f, s2 = 0.f;
    for (int m = start + w; m < end; m += 8) {
        float v = g_P[g_colS[m] * 256 + ch] + g_Q[g_rowS[m] * 256 + ch];
        s1 += v; s2 += v * v;
    }
    __shared__ float a1[8][32], a2[8][32];
    a1[w][lane] = s1; a2[w][lane] = s2;
    __syncthreads();
    if (w == 0) {
#pragma unroll
        for (int t = 1; t < 8; t++) { s1 += a1[t][lane]; s2 += a2[t][lane]; }
        int cnti = end - start; if (cnti < 1) cnti = 1;
        float cnt  = (float)cnti;
        float mean = s1 / cnt;
        float var  = fmaxf(s2 / cnt - mean * mean, 0.f);
        g_mean1[g * 256 + ch] = mean;
        g_rstd1[g * 256 + ch] = rsqrtf(var + EPS);
    }
}

// ---------------- K7: h2 via mma.sync bf16 3-term split ----------------------
// Block: 256 threads (8 warps), M=128 edges, N=64, K=256 in 8 chunks of 32.
// smem pitch 20 b32 per row (conflict-free fragment loads).
__global__ void __launch_bounds__(256) k_gemm2(const float* __restrict__ W2, int E) {
    __shared__ uint32_t Ah[128 * 20];
    __shared__ uint32_t Al[128 * 20];
    __shared__ uint32_t Bh[64 * 20];
    __shared__ uint32_t Bl[64 * 20];
    __shared__ int cS[128], rS[128], sS[128];
    int tid = threadIdx.x;
    int m0  = blockIdx.x * 128;
    int w    = tid >> 5;
    int lane = tid & 31;
    int gq   = lane >> 2;     // 0..7
    int tig  = lane & 3;      // 0..3
    if (tid < 128) {
        int m = m0 + tid; if (m >= E) m = E - 1;
        cS[tid] = g_colS[m]; rS[tid] = g_rowS[m]; sS[tid] = g_segS[m];
    }
    __syncthreads();

    float acc[8][4];
#pragma unroll
    for (int i = 0; i < 8; i++)
#pragma unroll
        for (int j = 0; j < 4; j++) acc[i][j] = 0.f;

    int rA   = tid >> 1;       // A-stage row 0..127
    int half = tid & 1;        // k half (16 cols)

    for (int kc = 0; kc < 8; kc++) {
        // ---- stage A: gather + normalize + relu + bf16 split (128 x 32) ----
        {
            int c = cS[rA], r = rS[rA], s = sS[rA];
            int kb = kc * 32 + half * 16;
#pragma unroll
            for (int q = 0; q < 4; q++) {
                int ko = kb + q * 4;
                float4 p  = *(const float4*)&g_P[c * 256 + ko];
                float4 qv = *(const float4*)&g_Q[r * 256 + ko];
                float4 mu = *(const float4*)&g_mean1[s * 256 + ko];
                float4 rs = *(const float4*)&g_rstd1[s * 256 + ko];
                float v0 = fmaxf((p.x + qv.x - mu.x) * rs.x, 0.f);
                float v1 = fmaxf((p.y + qv.y - mu.y) * rs.y, 0.f);
                float v2 = fmaxf((p.z + qv.z - mu.z) * rs.z, 0.f);
                float v3 = fmaxf((p.w + qv.w - mu.w) * rs.w, 0.f);
                float h0, l0, h1, l1, h2, l2, h3, l3;
                bsplit(v0, h0, l0); bsplit(v1, h1, l1);
                bsplit(v2, h2, l2); bsplit(v3, h3, l3);
                int o = rA * 20 + half * 8 + q * 2;
                Ah[o]     = pkbf(h0, h1);
                Ah[o + 1] = pkbf(h2, h3);
                Al[o]     = pkbf(l0, l1);
                Al[o + 1] = pkbf(l2, l3);
            }
        }
        // ---- stage B: W2 chunk [32 k x 64 n] -> [n][k] bf16 hi/lo ----------
#pragma unroll
        for (int idx = tid; idx < 1024; idx += 256) {
            int k2 = idx >> 6;         // 0..15 (k pair)
            int n  = idx & 63;
            int kk = kc * 32 + k2 * 2;
            float wa = W2[kk * 64 + n];
            float wb = W2[(kk + 1) * 64 + n];
            float ha, la, hb, lb;
            bsplit(wa, ha, la); bsplit(wb, hb, lb);
            Bh[n * 20 + k2] = pkbf(ha, hb);
            Bl[n * 20 + k2] = pkbf(la, lb);
        }
        __syncthreads();
        // ---- MMA: per warp rows [w*16, w*16+16), 2 k-steps, 8 n-tiles -------
        int r0 = w * 16;
#pragma unroll
        for (int ks = 0; ks < 2; ks++) {
            int kb = ks * 8;
            uint32_t ah0 = Ah[(r0 + gq) * 20 + kb + tig];
            uint32_t ah1 = Ah[(r0 + gq + 8) * 20 + kb + tig];
            uint32_t ah2 = Ah[(r0 + gq) * 20 + kb + tig + 4];
            uint32_t ah3 = Ah[(r0 + gq + 8) * 20 + kb + tig + 4];
            uint32_t al0 = Al[(r0 + gq) * 20 + kb + tig];
            uint32_t al1 = Al[(r0 + gq + 8) * 20 + kb + tig];
            uint32_t al2 = Al[(r0 + gq) * 20 + kb + tig + 4];
            uint32_t al3 = Al[(r0 + gq + 8) * 20 + kb + tig + 4];
#pragma unroll
            for (int nt = 0; nt < 8; nt++) {
                int nrow = nt * 8 + gq;
                uint32_t bh0 = Bh[nrow * 20 + kb + tig];
                uint32_t bh1 = Bh[nrow * 20 + kb + tig + 4];
                uint32_t bl0 = Bl[nrow * 20 + kb + tig];
                uint32_t bl1 = Bl[nrow * 20 + kb + tig + 4];
                mma16816(acc[nt], ah0, ah1, ah2, ah3, bh0, bh1);
                mma16816(acc[nt], ah0, ah1, ah2, ah3, bl0, bl1);
                mma16816(acc[nt], al0, al1, al2, al3, bh0, bh1);
            }
        }
        __syncthreads();
    }
    // ---- epilogue: D -> g_h2 -------------------------------------------------
    int row0 = m0 + w * 16 + gq;
    int row1 = row0 + 8;
#pragma unroll
    for (int nt = 0; nt < 8; nt++) {
        int cidx = nt * 8 + tig * 2;
        if (row0 < E)
            *(float2*)&g_h2[(size_t)row0 * 64 + cidx] = make_float2(acc[nt][0], acc[nt][1]);
        if (row1 < E)
            *(float2*)&g_h2[(size_t)row1 * 64 + cidx] = make_float2(acc[nt][2], acc[nt][3]);
    }
}

// ---------------- K8: stats of h2 --------------------------------------------
__global__ void k_stats2() {
    int g  = blockIdx.x;
    int c0 = blockIdx.y * 32;
    int lane = threadIdx.x & 31, w = threadIdx.x >> 5;
    int start = g_off[g], end = g_off[g + 1];
    int ch = c0 + lane;
    float s1 = 0.f, s2 = 0.f;
    for (int m = start + w; m < end; m += 8) {
        float v = g_h2[(size_t)m * 64 + ch];
        s1 += v; s2 += v * v;
    }
    __shared__ float a1[8][32], a2[8][32];
    a1[w][lane] = s1; a2[w][lane] = s2;
    __syncthreads();
    if (w == 0) {
#pragma unroll
        for (int t = 1; t < 8; t++) { s1 += a1[t][lane]; s2 += a2[t][lane]; }
        int cnti = end - start; if (cnti < 1) cnti = 1;
        float cnt  = (float)cnti;
        float mean = s1 / cnt;
        float var  = fmaxf(s2 / cnt - mean * mean, 0.f);
        g_mean2[g * 64 + ch] = mean;
        g_rstd2[g * 64 + ch] = rsqrtf(var + EPS);
    }
}

// ---------------- K9: out[perm[m]] = relu(norm2(h2)) . W3 + b3 ---------------
__global__ void k_final(const float* __restrict__ W3,
                        const float* __restrict__ b3,
                        float* __restrict__ out, int E) {
    __shared__ __align__(16) float sm[128 * 65];
    __shared__ float w3s[64];
    __shared__ int   sS[128];
    int tid = threadIdx.x;   // 128
    int m0  = blockIdx.x * 128;
    if (tid < 64) w3s[tid] = W3[tid];
    {
        int m = m0 + tid; if (m >= E) m = E - 1;
        sS[tid] = g_segS[m];
    }
    __syncthreads();
#pragma unroll
    for (int t = tid; t < 128 * 16; t += 128) {
        int rr = t >> 4, q = t & 15;
        int m = m0 + rr; if (m >= E) m = E - 1;
        float4 v  = *(const float4*)&g_h2[(size_t)m * 64 + q * 4];
        int s = sS[rr];
        float4 mu = *(const float4*)&g_mean2[s * 64 + q * 4];
        float4 rs = *(const float4*)&g_rstd2[s * 64 + q * 4];
        float* d = &sm[rr * 65 + q * 4];
        d[0] = fmaxf((v.x - mu.x) * rs.x, 0.f);
        d[1] = fmaxf((v.y - mu.y) * rs.y, 0.f);
        d[2] = fmaxf((v.z - mu.z) * rs.z, 0.f);
        d[3] = fmaxf((v.w - mu.w) * rs.w, 0.f);
    }
    __syncthreads();
    int m = m0 + tid;
    if (m < E) {
        float acc = 0.f;
#pragma unroll
        for (int k = 0; k < 64; k++) acc += sm[tid * 65 + k] * w3s[k];
        out[g_perm[m]] = acc + b3[0];
    }
}

// ---------------- launch -------------------------------------------------------
extern "C" void kernel_launch(void* const* d_in, const int* in_sizes, int n_in,
                              void* d_out, int out_size) {
    const float* emb = (const float*)d_in[0];
    const void*  ei  = d_in[1];
    const void*  bt  = d_in[2];
    const float* W1  = (const float*)d_in[3];
    // d_in[4] = b1 : cancels exactly through affine-free InstanceNorm
    const float* W2  = (const float*)d_in[5];
    // d_in[6] = b2 : cancels exactly through affine-free InstanceNorm
    const float* W3  = (const float*)d_in[7];
    const float* b3  = (const float*)d_in[8];
    float* out = (float*)d_out;

    int Nn = in_sizes[0] / 64;
    int E  = in_sizes[1] / 2;

    k_zero<<<(NMAX + 1023) / 1024, 1024>>>();                    // 1
    k_edges<<<(E + 255) / 256, 256>>>(ei, E, Nn);                // 2
    k_scan_node<<<1, 1024>>>(bt, E, Nn);                         // 3
    dim3 gPQ((Nn + 127) / 128, 4, 2);
    k_pq<<<gPQ, 128>>>(emb, W1, Nn);                             // 4 (profiled)
    k_scatter<<<(E + 255) / 256, 256>>>(bt, E);                  // 5
    k_stats1<<<dim3(128, 8), 256>>>();                           // 6
    k_gemm2<<<(E + 127) / 128, 256>>>(W2, E);                    // 7
    k_stats2<<<dim3(128, 2), 256>>>();                           // 8
    k_final<<<(E + 127) / 128, 128>>>(W3, b3, out, E);           // 9
}